// round 4
// baseline (speedup 1.0000x reference)
#include <cuda_runtime.h>
#include <math.h>

// Fused dot + softmax. Dot body identical to the 82.4us R1 kernel.
// Publication protocol (no __threadfence -> no CCTL.IVALL L1-flush storm):
//   - energy published with st.global.cg (writes through to L2)
//   - per-b arrival counter bumped with atom.add.acq_rel.gpu.u32
//     (release: orders the energy store; acquire on the last arrival:
//      orders the softmax row reads)
//   - softmax reads via __ldcg (L2), so L1 staleness is irrelevant.

__device__ unsigned int g_cnt[64];   // zero-init; self-resetting each launch

__global__ void __launch_bounds__(256) attn_fused_kernel(
    const float* __restrict__ hidden,   // [64, 1024]
    const float* __restrict__ enc,      // [2048, 64, 1024]
    float* __restrict__ out)            // [64, 2048] energies -> softmax in place
{
    int gwarp = (blockIdx.x * blockDim.x + threadIdx.x) >> 5;   // 0..131071
    int lane  = threadIdx.x & 31;

    int b = gwarp & 63;
    int s = gwarp >> 6;

    const float4* row = reinterpret_cast<const float4*>(enc + (size_t)gwarp * 1024);
    const float4* h   = reinterpret_cast<const float4*>(hidden + (size_t)b * 1024);

    float acc = 0.0f;
#pragma unroll
    for (int i = 0; i < 8; i++) {
        float4 e  = row[lane + i * 32];
        float4 hv = __ldg(&h[lane + i * 32]);
        acc = fmaf(e.x, hv.x, acc);
        acc = fmaf(e.y, hv.y, acc);
        acc = fmaf(e.z, hv.z, acc);
        acc = fmaf(e.w, hv.w, acc);
    }
#pragma unroll
    for (int o = 16; o; o >>= 1)
        acc += __shfl_xor_sync(0xffffffffu, acc, o);

    float* p = out + (size_t)b * 2048;

    // Publish energy (L2-visible), then acq_rel arrival on per-b counter.
    int last = 0;
    if (lane == 0) {
        asm volatile("st.global.cg.f32 [%0], %1;"
                     :: "l"(p + s), "f"(acc) : "memory");
        unsigned int old;
        asm volatile("atom.add.acq_rel.gpu.u32 %0, [%1], %2;"
                     : "=r"(old) : "l"(&g_cnt[b]), "r"(1u) : "memory");
        last = (old == 2047u);
    }
    last = __shfl_sync(0xffffffffu, last, 0);
    if (!last) return;

    // Last arrival for batch b: all 2048 energies are L2-visible (acquire).
    if (lane == 0) g_cnt[b] = 0;     // reset for next graph replay

    const float4* pv = reinterpret_cast<const float4*>(p);

    // Pass 1: max
    float m = -INFINITY;
    for (int i = lane; i < 512; i += 32) {
        float4 v = __ldcg(&pv[i]);
        m = fmaxf(m, fmaxf(fmaxf(v.x, v.y), fmaxf(v.z, v.w)));
    }
#pragma unroll
    for (int o = 16; o; o >>= 1)
        m = fmaxf(m, __shfl_xor_sync(0xffffffffu, m, o));

    // Pass 2: sum of exp
    float sum = 0.0f;
    for (int i = lane; i < 512; i += 32) {
        float4 v = __ldcg(&pv[i]);
        sum += __expf(v.x - m) + __expf(v.y - m) +
               __expf(v.z - m) + __expf(v.w - m);
    }
#pragma unroll
    for (int o = 16; o; o >>= 1)
        sum += __shfl_xor_sync(0xffffffffu, sum, o);
    float inv = 1.0f / sum;

    // Pass 3: normalized probabilities
    float4* pw = reinterpret_cast<float4*>(p);
    for (int i = lane; i < 512; i += 32) {
        float4 v = __ldcg(&pv[i]);
        v.x = __expf(v.x - m) * inv;
        v.y = __expf(v.y - m) * inv;
        v.z = __expf(v.z - m) * inv;
        v.w = __expf(v.w - m) * inv;
        pw[i] = v;
    }
}

extern "C" void kernel_launch(void* const* d_in, const int* in_sizes, int n_in,
                              void* d_out, int out_size)
{
    const float* hidden = (const float*)d_in[0];   // [1, 64, 1024]
    const float* enc    = (const float*)d_in[1];   // [2048, 64, 1024]
    float* out          = (float*)d_out;           // [64, 1, 2048]

    attn_fused_kernel<<<16384, 256>>>(hidden, enc, out);
}

// round 5
// speedup vs baseline: 1.9564x; 1.9564x over previous
#include <cuda_runtime.h>
#include <math.h>

// Phase 1: energies[b*2048 + s] = dot(hidden[b,:], enc[s,b,:])
// EXACT R1 structure (known 77.8us, ~6.9 TB/s): 1 warp/row, 8 independent
// float4 loads in flight, low regs -> high occupancy.
__global__ void __launch_bounds__(256) dot_kernel(
    const float* __restrict__ hidden,   // [64, 1024]
    const float* __restrict__ enc,      // [2048, 64, 1024]
    float* __restrict__ energies)       // [64, 2048]
{
    int gwarp = (blockIdx.x * blockDim.x + threadIdx.x) >> 5;   // 0..131071
    int lane  = threadIdx.x & 31;

    int b = gwarp & 63;
    int s = gwarp >> 6;

    const float4* row = reinterpret_cast<const float4*>(enc + (size_t)gwarp * 1024);
    const float4* h   = reinterpret_cast<const float4*>(hidden + (size_t)b * 1024);

    float acc = 0.0f;
#pragma unroll
    for (int i = 0; i < 8; i++) {
        float4 e  = row[lane + i * 32];
        float4 hv = __ldg(&h[lane + i * 32]);
        acc = fmaf(e.x, hv.x, acc);
        acc = fmaf(e.y, hv.y, acc);
        acc = fmaf(e.z, hv.z, acc);
        acc = fmaf(e.w, hv.w, acc);
    }
#pragma unroll
    for (int o = 16; o; o >>= 1)
        acc += __shfl_xor_sync(0xffffffffu, acc, o);

    if (lane == 0)
        energies[b * 2048 + s] = acc;
}

// Phase 2: softmax over S=2048 per batch row, launched with PDL so its
// prologue overlaps the dot kernel's tail. cudaGridDependencySynchronize()
// guarantees all dot stores are visible before the energies are read.
__global__ void __launch_bounds__(1024) softmax_kernel(float* __restrict__ out)
{
    __shared__ float red[32];

    int b    = blockIdx.x;
    int tid  = threadIdx.x;
    int lane = tid & 31;
    int wid  = tid >> 5;
    float* p = out + (size_t)b * 2048;

    cudaGridDependencySynchronize();   // wait for dot_kernel completion/visibility

    float v0 = p[tid];
    float v1 = p[tid + 1024];

    // --- max reduce ---
    float m = fmaxf(v0, v1);
#pragma unroll
    for (int o = 16; o; o >>= 1)
        m = fmaxf(m, __shfl_xor_sync(0xffffffffu, m, o));
    if (lane == 0) red[wid] = m;
    __syncthreads();
    if (tid < 32) {
        float x = red[tid];
#pragma unroll
        for (int o = 16; o; o >>= 1)
            x = fmaxf(x, __shfl_xor_sync(0xffffffffu, x, o));
        if (tid == 0) red[0] = x;
    }
    __syncthreads();
    m = red[0];
    __syncthreads();

    // --- exp + sum reduce ---
    v0 = __expf(v0 - m);
    v1 = __expf(v1 - m);
    float s = v0 + v1;
#pragma unroll
    for (int o = 16; o; o >>= 1)
        s += __shfl_xor_sync(0xffffffffu, s, o);
    if (lane == 0) red[wid] = s;
    __syncthreads();
    if (tid < 32) {
        float x = red[tid];
#pragma unroll
        for (int o = 16; o; o >>= 1)
            x += __shfl_xor_sync(0xffffffffu, x, o);
        if (tid == 0) red[0] = x;
    }
    __syncthreads();
    float inv = 1.0f / red[0];

    p[tid]        = v0 * inv;
    p[tid + 1024] = v1 * inv;
}

extern "C" void kernel_launch(void* const* d_in, const int* in_sizes, int n_in,
                              void* d_out, int out_size)
{
    const float* hidden = (const float*)d_in[0];   // [1, 64, 1024]
    const float* enc    = (const float*)d_in[1];   // [2048, 64, 1024]
    float* out          = (float*)d_out;           // [64, 1, 2048]

    dot_kernel<<<16384, 256>>>(hidden, enc, out);

    // PDL launch: softmax prologue overlaps dot tail; grid-dependency sync
    // inside the kernel enforces ordering.
    cudaLaunchConfig_t cfg = {};
    cfg.gridDim  = dim3(64, 1, 1);
    cfg.blockDim = dim3(1024, 1, 1);
    cfg.dynamicSmemBytes = 0;
    cfg.stream = 0;
    cudaLaunchAttribute attrs[1];
    attrs[0].id = cudaLaunchAttributeProgrammaticStreamSerialization;
    attrs[0].val.programmaticStreamSerializationAllowed = 1;
    cfg.attrs = attrs;
    cfg.numAttrs = 1;
    cudaLaunchKernelEx(&cfg, softmax_kernel, out);
}

// round 6
// speedup vs baseline: 1.9602x; 1.0020x over previous
#include <cuda_runtime.h>
#include <math.h>

// Phase 1: energies[b*2048 + s] = dot(hidden[b,:], enc[s,b,:])
// R1 structure (known ~77.8us): 1 warp/row, 8 independent float4 loads in
// flight. Only change: enc streamed with __ldcs (evict-first; zero reuse).
__global__ void __launch_bounds__(256) dot_kernel(
    const float* __restrict__ hidden,   // [64, 1024]
    const float* __restrict__ enc,      // [2048, 64, 1024]
    float* __restrict__ energies)       // [64, 2048]
{
    int gwarp = (blockIdx.x * blockDim.x + threadIdx.x) >> 5;   // 0..131071
    int lane  = threadIdx.x & 31;

    int b = gwarp & 63;
    int s = gwarp >> 6;

    const float4* row = reinterpret_cast<const float4*>(enc + (size_t)gwarp * 1024);
    const float4* h   = reinterpret_cast<const float4*>(hidden + (size_t)b * 1024);

    float acc = 0.0f;
#pragma unroll
    for (int i = 0; i < 8; i++) {
        float4 e  = __ldcs(&row[lane + i * 32]);
        float4 hv = __ldg(&h[lane + i * 32]);
        acc = fmaf(e.x, hv.x, acc);
        acc = fmaf(e.y, hv.y, acc);
        acc = fmaf(e.z, hv.z, acc);
        acc = fmaf(e.w, hv.w, acc);
    }
#pragma unroll
    for (int o = 16; o; o >>= 1)
        acc += __shfl_xor_sync(0xffffffffu, acc, o);

    if (lane == 0)
        energies[b * 2048 + s] = acc;
}

// Phase 2: warp-per-row softmax, no __syncthreads, single memory round-trip.
// 64 rows -> 64 CTAs of 1 warp. Each lane owns 16 float4 = 64 values in regs.
__global__ void __launch_bounds__(32) softmax_kernel(float* __restrict__ out)
{
    int b    = blockIdx.x;
    int lane = threadIdx.x;
    float* p = out + (size_t)b * 2048;

    cudaGridDependencySynchronize();   // wait for dot_kernel stores

    const float4* pv = reinterpret_cast<const float4*>(p);
    float4 v[16];
#pragma unroll
    for (int i = 0; i < 16; i++)
        v[i] = __ldcg(&pv[lane + i * 32]);

    // --- max: register tree, then 5 shuffles ---
    float m = -INFINITY;
#pragma unroll
    for (int i = 0; i < 16; i++)
        m = fmaxf(m, fmaxf(fmaxf(v[i].x, v[i].y), fmaxf(v[i].z, v[i].w)));
#pragma unroll
    for (int o = 16; o; o >>= 1)
        m = fmaxf(m, __shfl_xor_sync(0xffffffffu, m, o));

    // --- exp in place + sum ---
    float s = 0.0f;
#pragma unroll
    for (int i = 0; i < 16; i++) {
        v[i].x = __expf(v[i].x - m);
        v[i].y = __expf(v[i].y - m);
        v[i].z = __expf(v[i].z - m);
        v[i].w = __expf(v[i].w - m);
        s += (v[i].x + v[i].y) + (v[i].z + v[i].w);
    }
#pragma unroll
    for (int o = 16; o; o >>= 1)
        s += __shfl_xor_sync(0xffffffffu, s, o);
    float inv = 1.0f / s;

    float4* pw = reinterpret_cast<float4*>(p);
#pragma unroll
    for (int i = 0; i < 16; i++) {
        float4 w = v[i];
        w.x *= inv; w.y *= inv; w.z *= inv; w.w *= inv;
        pw[lane + i * 32] = w;
    }
}

extern "C" void kernel_launch(void* const* d_in, const int* in_sizes, int n_in,
                              void* d_out, int out_size)
{
    const float* hidden = (const float*)d_in[0];   // [1, 64, 1024]
    const float* enc    = (const float*)d_in[1];   // [2048, 64, 1024]
    float* out          = (float*)d_out;           // [64, 1, 2048]

    dot_kernel<<<16384, 256>>>(hidden, enc, out);

    // PDL launch: hides softmax launch latency behind dot tail.
    cudaLaunchConfig_t cfg = {};
    cfg.gridDim  = dim3(64, 1, 1);
    cfg.blockDim = dim3(32, 1, 1);
    cfg.dynamicSmemBytes = 0;
    cfg.stream = 0;
    cudaLaunchAttribute attrs[1];
    attrs[0].id = cudaLaunchAttributeProgrammaticStreamSerialization;
    attrs[0].val.programmaticStreamSerializationAllowed = 1;
    cfg.attrs = attrs;
    cfg.numAttrs = 1;
    cudaLaunchKernelEx(&cfg, softmax_kernel, out);
}

// round 7
// speedup vs baseline: 2.0000x; 1.0203x over previous
#include <cuda_runtime.h>
#include <math.h>

// Phase 1: energies[b*2048 + s] = dot(hidden[b,:], enc[s,b,:])
// Block = (b, s_chunk): all 8 warps share one b. hidden[b] (4KB) is staged in
// shared memory ONCE per block, so hidden reads never touch the LTS path
// (L2 throughput cap ~6300 B/cyc is path-independent and was being split
// between the enc stream and per-warp hidden refetches).
__global__ void __launch_bounds__(256) dot_kernel(
    const float* __restrict__ hidden,   // [64, 1024]
    const float* __restrict__ enc,      // [2048, 64, 1024]
    float* __restrict__ energies)       // [64, 2048]
{
    __shared__ float4 sh[256];          // hidden[b] : 1024 floats = 4KB

    int b      = blockIdx.x >> 8;       // 0..63
    int schunk = blockIdx.x & 255;      // 0..255

    // cooperative load of hidden[b] into smem (1 float4 per thread)
    sh[threadIdx.x] =
        reinterpret_cast<const float4*>(hidden + (size_t)b * 1024)[threadIdx.x];
    __syncthreads();

    int warp = threadIdx.x >> 5;
    int lane = threadIdx.x & 31;
    int s    = schunk * 8 + warp;

    const float4* row = reinterpret_cast<const float4*>(
        enc + ((size_t)s * 64 + b) * 1024);

    float acc = 0.0f;
#pragma unroll
    for (int i = 0; i < 8; i++) {
        float4 e  = __ldcs(&row[lane + i * 32]);   // evict-first stream
        float4 hv = sh[lane + i * 32];             // LDS, conflict-free
        acc = fmaf(e.x, hv.x, acc);
        acc = fmaf(e.y, hv.y, acc);
        acc = fmaf(e.z, hv.z, acc);
        acc = fmaf(e.w, hv.w, acc);
    }
#pragma unroll
    for (int o = 16; o; o >>= 1)
        acc += __shfl_xor_sync(0xffffffffu, acc, o);

    if (lane == 0)
        energies[b * 2048 + s] = acc;
}

// Phase 2: warp-per-row softmax (no barriers), PDL-overlapped with dot tail.
__global__ void __launch_bounds__(32) softmax_kernel(float* __restrict__ out)
{
    int b    = blockIdx.x;
    int lane = threadIdx.x;
    float* p = out + (size_t)b * 2048;

    cudaGridDependencySynchronize();   // wait for dot_kernel stores

    const float4* pv = reinterpret_cast<const float4*>(p);
    float4 v[16];
#pragma unroll
    for (int i = 0; i < 16; i++)
        v[i] = __ldcg(&pv[lane + i * 32]);

    float m = -INFINITY;
#pragma unroll
    for (int i = 0; i < 16; i++)
        m = fmaxf(m, fmaxf(fmaxf(v[i].x, v[i].y), fmaxf(v[i].z, v[i].w)));
#pragma unroll
    for (int o = 16; o; o >>= 1)
        m = fmaxf(m, __shfl_xor_sync(0xffffffffu, m, o));

    float s = 0.0f;
#pragma unroll
    for (int i = 0; i < 16; i++) {
        v[i].x = __expf(v[i].x - m);
        v[i].y = __expf(v[i].y - m);
        v[i].z = __expf(v[i].z - m);
        v[i].w = __expf(v[i].w - m);
        s += (v[i].x + v[i].y) + (v[i].z + v[i].w);
    }
#pragma unroll
    for (int o = 16; o; o >>= 1)
        s += __shfl_xor_sync(0xffffffffu, s, o);
    float inv = 1.0f / s;

    float4* pw = reinterpret_cast<float4*>(p);
#pragma unroll
    for (int i = 0; i < 16; i++) {
        float4 w = v[i];
        w.x *= inv; w.y *= inv; w.z *= inv; w.w *= inv;
        pw[lane + i * 32] = w;
    }
}

extern "C" void kernel_launch(void* const* d_in, const int* in_sizes, int n_in,
                              void* d_out, int out_size)
{
    const float* hidden = (const float*)d_in[0];   // [1, 64, 1024]
    const float* enc    = (const float*)d_in[1];   // [2048, 64, 1024]
    float* out          = (float*)d_out;           // [64, 1, 2048]

    dot_kernel<<<16384, 256>>>(hidden, enc, out);

    cudaLaunchConfig_t cfg = {};
    cfg.gridDim  = dim3(64, 1, 1);
    cfg.blockDim = dim3(32, 1, 1);
    cfg.dynamicSmemBytes = 0;
    cfg.stream = 0;
    cudaLaunchAttribute attrs[1];
    attrs[0].id = cudaLaunchAttributeProgrammaticStreamSerialization;
    attrs[0].val.programmaticStreamSerializationAllowed = 1;
    cfg.attrs = attrs;
    cfg.numAttrs = 1;
    cudaLaunchKernelEx(&cfg, softmax_kernel, out);
}